// round 1
// baseline (speedup 1.0000x reference)
#include <cuda_runtime.h>
#include <cstdint>

// Problem constants
#define B_       128
#define T_IN     240
#define T_OUT    30
#define D_       128
#define H_       256
#define G3       768              // 3*H
#define STRIDE_  8
#define ENC_STEPS (T_IN * B_)     // 30720
#define DEC_STEPS (T_OUT * B_)    // 3840

// Scratch: precomputed input projections gi = x @ Wih^T + b_ih
__device__ float GI_enc[ENC_STEPS * G3];   // ~94.4 MB
__device__ float GI_dec[DEC_STEPS * G3];   // ~11.8 MB

// ---------------------------------------------------------------------------
// Kernel 1: GI GEMM.  GI[s][row] = b_ih[row] + sum_d X[s,d] * Wih[row][d]
// Encoder: X[s] = x[s&127, s>>7, :]      (s = t*128 + b)
// Decoder: X[s] = x[s&127, (s>>7)*8, :]
// ---------------------------------------------------------------------------
#define S_TILE     32
#define ENC_BLOCKS (ENC_STEPS / S_TILE)   // 960
#define DEC_BLOCKS (DEC_STEPS / S_TILE)   // 120

__global__ void __launch_bounds__(768, 1) gi_kernel(
    const float* __restrict__ x,
    const float* __restrict__ Wih_e, const float* __restrict__ bih_e,
    const float* __restrict__ Wih_d, const float* __restrict__ bih_d)
{
    __shared__ __align__(16) float Xs[S_TILE][D_];   // 16 KB

    bool enc = blockIdx.x < ENC_BLOCKS;
    int  sblk = enc ? blockIdx.x : blockIdx.x - ENC_BLOCKS;
    int  s0   = sblk * S_TILE;
    const float* W   = enc ? Wih_e : Wih_d;
    const float* bih = enc ? bih_e : bih_d;
    float*       GI  = enc ? GI_enc : GI_dec;
    int tstride = enc ? 1 : STRIDE_;

    int tid = threadIdx.x;

    // Load x tile (32 timesteps x 128)
    for (int idx = tid; idx < S_TILE * D_; idx += 768) {
        int i = idx >> 7;
        int k = idx & 127;
        int s = s0 + i;
        int b = s & 127;
        int t = (s >> 7) * tstride;
        Xs[i][k] = x[(size_t)b * (T_IN * D_) + (size_t)t * D_ + k];
    }
    __syncthreads();

    int row = tid;   // 0..767 (one weight row per thread)
    const float4* W4 = (const float4*)(W + (size_t)row * D_);

    float acc[S_TILE];
#pragma unroll
    for (int i = 0; i < S_TILE; i++) acc[i] = 0.f;

#pragma unroll 4
    for (int kk = 0; kk < D_ / 4; kk++) {
        float4 w = W4[kk];
#pragma unroll
        for (int i = 0; i < S_TILE; i++) {
            float4 xv = ((const float4*)Xs[i])[kk];
            acc[i] += w.x * xv.x + w.y * xv.y + w.z * xv.z + w.w * xv.w;
        }
    }

    float bv = bih[row];
#pragma unroll
    for (int i = 0; i < S_TILE; i++)
        GI[(size_t)(s0 + i) * G3 + row] = acc[i] + bv;
}

// ---------------------------------------------------------------------------
// Kernel 2: the serial GRU scans.  8-CTA cluster per scan, weights in
// registers (96 rows x 256 per CTA = 64 floats/thread @ 384 threads).
// CTA rank c owns h-indices [c*32, c*32+32): rows {c*32+i, 256+c*32+i,
// 512+c*32+i}.  Gates are computed locally by warp 0; only 32 h_new floats
// per CTA are broadcast to all 8 CTAs each step (st.shared::cluster),
// then one cluster barrier.
// ---------------------------------------------------------------------------
#define CLUSTER  8
#define NTHREADS 384

__device__ __forceinline__ uint32_t smem_u32(const void* p) {
    return (uint32_t)__cvta_generic_to_shared(p);
}
__device__ __forceinline__ uint32_t mapa_shared(uint32_t addr, uint32_t rank) {
    uint32_t r;
    asm volatile("mapa.shared::cluster.u32 %0, %1, %2;" : "=r"(r) : "r"(addr), "r"(rank));
    return r;
}
__device__ __forceinline__ void st_cluster_f32(uint32_t addr, float v) {
    asm volatile("st.shared::cluster.f32 [%0], %1;" :: "r"(addr), "f"(v) : "memory");
}
__device__ __forceinline__ void cluster_sync_() {
    asm volatile("barrier.cluster.arrive.aligned;" ::: "memory");
    asm volatile("barrier.cluster.wait.aligned;"   ::: "memory");
}
__device__ __forceinline__ float sigmoid_(float xv) {
    // 1/(1+e^{-x}); __expf(+inf)->inf -> rcp -> 0  (saturates correctly)
    return __fdividef(1.0f, 1.0f + __expf(-xv));
}
__device__ __forceinline__ float tanh_(float xv) {
    // tanh(x) = 1 - 2/(e^{2x}+1); saturates correctly at +-inf
    return 1.0f - __fdividef(2.0f, __expf(2.0f * xv) + 1.0f);
}

__global__ void __launch_bounds__(NTHREADS, 1) scan_kernel(
    const float* __restrict__ Whh_e, const float* __restrict__ bhh_e,
    const float* __restrict__ Whh_d, const float* __restrict__ bhh_d,
    float* __restrict__ out)
{
    __shared__ __align__(16) float hbuf[2][H_];
    __shared__ float partial[NTHREADS];

    bool enc = (blockIdx.x >> 3) == 0;   // cluster 0 = encoder, cluster 1 = decoder
    uint32_t crank;
    asm("mov.u32 %0, %%cluster_ctarank;" : "=r"(crank));

    const float* Whh = enc ? Whh_e : Whh_d;
    const float* bhh = enc ? bhh_e : bhh_d;
    const float* GI  = enc ? GI_enc : GI_dec;
    int    nsteps = enc ? ENC_STEPS : DEC_STEPS;
    float* outp   = enc ? out : (out + 240 * H_);

    int tid  = threadIdx.x;
    int l    = tid % 96;        // local weight row
    int q    = tid / 96;        // input quarter (0..3), warp-uniform
    int part = l >> 5;          // 0=r,1=z,2=n
    int i0l  = l & 31;
    int Grow = part * 256 + (int)crank * 32 + i0l;   // global W_hh row

    // ---- load this thread's 64 weights into registers ----
    float w[64];
    {
        const float4* Wr = (const float4*)(Whh + (size_t)Grow * H_ + q * 64);
#pragma unroll
        for (int kk = 0; kk < 16; kk++) {
            float4 v = Wr[kk];
            w[4*kk+0] = v.x; w[4*kk+1] = v.y; w[4*kk+2] = v.z; w[4*kk+3] = v.w;
        }
    }

    // ---- gate-lane (warp 0) setup ----
    bool gatelane = (tid < 32);
    int  j = (int)crank * 32 + tid;   // global h index (valid for gate lanes)
    float bh_r = 0.f, bh_z = 0.f, bh_n = 0.f;
    uint32_t remaddr0[CLUSTER], remaddr1[CLUSTER];
    if (gatelane) {
        bh_r = bhh[j];
        bh_z = bhh[256 + j];
        bh_n = bhh[512 + j];
        uint32_t a0 = smem_u32(&hbuf[0][j]);
        uint32_t a1 = smem_u32(&hbuf[1][j]);
#pragma unroll
        for (int rk = 0; rk < CLUSTER; rk++) {
            remaddr0[rk] = mapa_shared(a0, rk);
            remaddr1[rk] = mapa_shared(a1, rk);
        }
    }

    // init h0 = 0
    if (tid < H_) hbuf[0][tid] = 0.f;
    __syncthreads();
    cluster_sync_();

    // prefetch gi for step 0
    float gi_r = 0.f, gi_z = 0.f, gi_n = 0.f;
    if (gatelane) {
        gi_r = __ldg(&GI[j]);
        gi_z = __ldg(&GI[256 + j]);
        gi_n = __ldg(&GI[512 + j]);
    }

    for (int s = 0; s < nsteps; s++) {
        int rd = s & 1;
        int wr = rd ^ 1;

        // ---- matvec: gh_partial = w . h[q*64 .. q*64+63] ----
        const float4* hp = (const float4*)(&hbuf[rd][q * 64]);
        float a0 = 0.f, a1 = 0.f, a2 = 0.f, a3 = 0.f;
#pragma unroll
        for (int kk = 0; kk < 16; kk++) {
            float4 hv = hp[kk];
            a0 += w[4*kk+0] * hv.x;
            a1 += w[4*kk+1] * hv.y;
            a2 += w[4*kk+2] * hv.z;
            a3 += w[4*kk+3] * hv.w;
        }
        partial[tid] = (a0 + a1) + (a2 + a3);

        // prefetch gi for next step (hidden under this step's sync/gates)
        float ngi_r = 0.f, ngi_z = 0.f, ngi_n = 0.f;
        if (gatelane && (s + 1) < nsteps) {
            const float* g = GI + (size_t)(s + 1) * G3;
            ngi_r = __ldg(&g[j]);
            ngi_z = __ldg(&g[256 + j]);
            ngi_n = __ldg(&g[512 + j]);
        }

        __syncthreads();

        if (gatelane) {
            int i0 = tid;
            float pr = 0.f, pz = 0.f, pn = 0.f;
#pragma unroll
            for (int qq = 0; qq < 4; qq++) {
                pr += partial[qq * 96 + i0];
                pz += partial[qq * 96 + 32 + i0];
                pn += partial[qq * 96 + 64 + i0];
            }
            float r    = sigmoid_(gi_r + pr + bh_r);
            float z    = sigmoid_(gi_z + pz + bh_z);
            float hold = hbuf[rd][j];
            float n    = tanh_(gi_n + r * (pn + bh_n));
            float hnew = n + z * (hold - n);   // (1-z)*n + z*h

            // broadcast h_new[j] into every CTA's write buffer
            if (wr == 0) {
#pragma unroll
                for (int rk = 0; rk < CLUSTER; rk++) st_cluster_f32(remaddr0[rk], hnew);
            } else {
#pragma unroll
                for (int rk = 0; rk < CLUSTER; rk++) st_cluster_f32(remaddr1[rk], hnew);
            }

            // outputs
            if (enc) {
                if ((s & 127) == 127)
                    outp[(size_t)(s >> 7) * H_ + j] = hnew;   // encoder_hidden_states[t]
            } else {
                // interped_seq[b, t, :] with s = t*128 + b
                outp[(size_t)(s & 127) * (T_OUT * H_) + (size_t)(s >> 7) * H_ + j] = hnew;
            }
        }

        gi_r = ngi_r; gi_z = ngi_z; gi_n = ngi_n;

        cluster_sync_();   // release h_new stores, all CTAs advance together
    }
}

// ---------------------------------------------------------------------------
// Launch
// ---------------------------------------------------------------------------
extern "C" void kernel_launch(void* const* d_in, const int* in_sizes, int n_in,
                              void* d_out, int out_size)
{
    const float* x     = (const float*)d_in[0];
    const float* Wih_e = (const float*)d_in[1];
    const float* Whh_e = (const float*)d_in[2];
    const float* bih_e = (const float*)d_in[3];
    const float* bhh_e = (const float*)d_in[4];
    const float* Wih_d = (const float*)d_in[5];
    const float* Whh_d = (const float*)d_in[6];
    const float* bih_d = (const float*)d_in[7];
    const float* bhh_d = (const float*)d_in[8];
    float* out = (float*)d_out;

    // 1) input projections (parallel GEMM)
    gi_kernel<<<ENC_BLOCKS + DEC_BLOCKS, 768>>>(x, Wih_e, bih_e, Wih_d, bih_d);

    // 2) serial scans: 2 clusters of 8 CTAs (encoder + decoder, concurrent)
    cudaLaunchConfig_t cfg = {};
    cfg.gridDim  = dim3(2 * CLUSTER, 1, 1);
    cfg.blockDim = dim3(NTHREADS, 1, 1);
    cfg.dynamicSmemBytes = 0;
    cfg.stream = 0;
    cudaLaunchAttribute attrs[1];
    attrs[0].id = cudaLaunchAttributeClusterDimension;
    attrs[0].val.clusterDim.x = CLUSTER;
    attrs[0].val.clusterDim.y = 1;
    attrs[0].val.clusterDim.z = 1;
    cfg.attrs = attrs;
    cfg.numAttrs = 1;
    cudaLaunchKernelEx(&cfg, scan_kernel, Whh_e, bhh_e, Whh_d, bhh_d, out);
}